// round 1
// baseline (speedup 1.0000x reference)
#include <cuda_runtime.h>
#include <cstddef>

#define DIM    1024
#define HEADS  16
#define DEPTH  64
#define BATCH  4
#define SEQ    2048
#define ROWS   (BATCH * SEQ)   // 8192

// ---------------- scratch (device globals; no allocation allowed) ----------
__device__ float g_Qh[(size_t)BATCH * HEADS * SEQ * DEPTH];  // [B,H,S,D]
__device__ float g_Kh[(size_t)BATCH * HEADS * SEQ * DEPTH];
__device__ float g_Vh[(size_t)BATCH * HEADS * SEQ * DEPTH];
__device__ float g_Att[(size_t)ROWS * DIM];                  // [B,S,DIM]

// ---------------------------------------------------------------------------
// SGEMM: C = A[M,K] @ B[K,N], M = gridDim.y*128, N = K = 1024.
// mode 0: C flat [M,N]. mode 1: C in [B,H,S,D] attention layout.
// 128x128 block tile, k-step 8, 8x8 micro-tile per thread, 256 threads.
// ---------------------------------------------------------------------------
__global__ void __launch_bounds__(256) sgemm_kernel(
    const float* __restrict__ A, const float* __restrict__ B,
    float* __restrict__ C, int mode)
{
    const int K = DIM, N = DIM;
    __shared__ float As[8][132];   // [k][m], padded vs bank conflicts
    __shared__ float Bs[8][128];   // [k][n]

    const int tid = threadIdx.x;
    const int tx = tid & 15, ty = tid >> 4;
    const int m0 = blockIdx.y << 7;
    const int n0 = blockIdx.x << 7;

    const int a_row = tid >> 1;            // 0..127
    const int a_k   = (tid & 1) << 2;      // 0 or 4
    const int b_k   = tid >> 5;            // 0..7
    const int b_n   = (tid & 31) << 2;     // 0..124

    const float* Ap = A + (size_t)(m0 + a_row) * K + a_k;
    const float* Bp = B + (size_t)b_k * N + n0 + b_n;

    float acc[8][8];
#pragma unroll
    for (int i = 0; i < 8; i++)
#pragma unroll
        for (int j = 0; j < 8; j++) acc[i][j] = 0.f;

    for (int kk = 0; kk < K; kk += 8) {
        float4 av = *(const float4*)(Ap + kk);
        float4 bv = *(const float4*)(Bp + (size_t)kk * N);
        __syncthreads();
        As[a_k + 0][a_row] = av.x;
        As[a_k + 1][a_row] = av.y;
        As[a_k + 2][a_row] = av.z;
        As[a_k + 3][a_row] = av.w;
        *(float4*)&Bs[b_k][b_n] = bv;
        __syncthreads();

#pragma unroll
        for (int k = 0; k < 8; k++) {
            float a[8], b[8];
            *(float4*)&a[0] = *(const float4*)&As[k][ty << 3];
            *(float4*)&a[4] = *(const float4*)&As[k][(ty << 3) + 4];
            *(float4*)&b[0] = *(const float4*)&Bs[k][tx << 3];
            *(float4*)&b[4] = *(const float4*)&Bs[k][(tx << 3) + 4];
#pragma unroll
            for (int i = 0; i < 8; i++)
#pragma unroll
                for (int j = 0; j < 8; j++)
                    acc[i][j] = fmaf(a[i], b[j], acc[i][j]);
        }
    }

    if (mode == 0) {
#pragma unroll
        for (int i = 0; i < 8; i++) {
            float* Cp = C + (size_t)(m0 + (ty << 3) + i) * N + n0 + (tx << 3);
            *(float4*)(Cp + 0) = make_float4(acc[i][0], acc[i][1], acc[i][2], acc[i][3]);
            *(float4*)(Cp + 4) = make_float4(acc[i][4], acc[i][5], acc[i][6], acc[i][7]);
        }
    } else {
        // scatter to [B,H,S,D]: row r = b*SEQ+s, col c = h*64+d
#pragma unroll
        for (int i = 0; i < 8; i++) {
            int r = m0 + (ty << 3) + i;
            int bb = r >> 11;          // / SEQ
            int s  = r & 2047;
#pragma unroll
            for (int j = 0; j < 8; j++) {
                int c = n0 + (tx << 3) + j;
                int h = c >> 6;
                int d = c & 63;
                size_t idx = (((size_t)(bb * HEADS + h) * SEQ + s) << 6) + d;
                C[idx] = acc[i][j];
            }
        }
    }
}

// ---------------------------------------------------------------------------
// Flash attention, fp32. One block = (b, h, 64-query tile). 256 threads,
// 16x16 layout, each thread owns a 4x4 tile of the 64x64 score/O blocks.
// Online softmax with -mask*1e9 key masking, scale 1/8.
// ---------------------------------------------------------------------------
#define FA_SMEM_FLOATS (4 * 64 * 68 + 64)
#define FA_SMEM_BYTES  (FA_SMEM_FLOATS * 4)

__global__ void __launch_bounds__(256) flash_kernel(
    const float* __restrict__ Qh, const float* __restrict__ Kh,
    const float* __restrict__ Vh, const float* __restrict__ Mask,
    float* __restrict__ Att)
{
    extern __shared__ float sm[];
    float* Qs = sm;                  // [64][68]  row-major [q][d]
    float* Kt = sm + 64 * 68;        // [64][68]  transposed [d][j]
    float* Vs = sm + 2 * 64 * 68;    // [64][68]  [j][d]
    float* Ps = sm + 3 * 64 * 68;    // [64][68]  [q][j]
    float* Ms = sm + 4 * 64 * 68;    // [64] key mask tile

    const int tid = threadIdx.x;
    const int tx = tid & 15, ty = tid >> 4;
    const int b = blockIdx.z, h = blockIdx.y, qt = blockIdx.x;

    const float* Qg = Qh + ((size_t)(b * HEADS + h) * SEQ + qt * 64) * DEPTH;
    const float* Kg = Kh + (size_t)(b * HEADS + h) * SEQ * DEPTH;
    const float* Vg = Vh + (size_t)(b * HEADS + h) * SEQ * DEPTH;
    const float* Mg = Mask + (size_t)b * SEQ;

    // load Q tile (64x64)
#pragma unroll
    for (int it = 0; it < 4; it++) {
        int idx = tid + it * 256;
        int row = idx >> 4;
        int d0  = (idx & 15) << 2;
        *(float4*)&Qs[row * 68 + d0] = *(const float4*)(Qg + row * DEPTH + d0);
    }

    float O[4][4];
    float m_r[4], l_r[4];
#pragma unroll
    for (int r = 0; r < 4; r++) {
        m_r[r] = -1e30f; l_r[r] = 0.f;
#pragma unroll
        for (int c = 0; c < 4; c++) O[r][c] = 0.f;
    }

    for (int kt = 0; kt < SEQ / 64; kt++) {
        __syncthreads();   // previous iteration done reading Vs/Ps; Qs writes done
        const float* Kgt = Kg + kt * 64 * DEPTH;
        const float* Vgt = Vg + kt * 64 * DEPTH;
#pragma unroll
        for (int it = 0; it < 4; it++) {
            int idx = tid + it * 256;
            int row = idx >> 4;
            int d0  = (idx & 15) << 2;
            float4 kv = *(const float4*)(Kgt + row * DEPTH + d0);
            Kt[(d0 + 0) * 68 + row] = kv.x;
            Kt[(d0 + 1) * 68 + row] = kv.y;
            Kt[(d0 + 2) * 68 + row] = kv.z;
            Kt[(d0 + 3) * 68 + row] = kv.w;
            *(float4*)&Vs[row * 68 + d0] = *(const float4*)(Vgt + row * DEPTH + d0);
        }
        if (tid < 64) Ms[tid] = Mg[kt * 64 + tid];
        __syncthreads();

        // S = Q @ K^T  (outer product over d)
        float s[4][4];
#pragma unroll
        for (int r = 0; r < 4; r++)
#pragma unroll
            for (int c = 0; c < 4; c++) s[r][c] = 0.f;

#pragma unroll 4
        for (int d = 0; d < 64; d++) {
            float4 kb = *(const float4*)&Kt[d * 68 + (tx << 2)];
#pragma unroll
            for (int r = 0; r < 4; r++) {
                float a = Qs[((ty << 2) + r) * 68 + d];
                s[r][0] = fmaf(a, kb.x, s[r][0]);
                s[r][1] = fmaf(a, kb.y, s[r][1]);
                s[r][2] = fmaf(a, kb.z, s[r][2]);
                s[r][3] = fmaf(a, kb.w, s[r][3]);
            }
        }

        // scale, mask, online softmax
        float msk[4];
#pragma unroll
        for (int c = 0; c < 4; c++) msk[c] = Ms[(tx << 2) + c] * 1e9f;

#pragma unroll
        for (int r = 0; r < 4; r++) {
            float mloc = -1e30f;
#pragma unroll
            for (int c = 0; c < 4; c++) {
                float sv = fmaf(s[r][c], 0.125f, -msk[c]);
                s[r][c] = sv;
                mloc = fmaxf(mloc, sv);
            }
#pragma unroll
            for (int o = 8; o > 0; o >>= 1)
                mloc = fmaxf(mloc, __shfl_xor_sync(0xffffffffu, mloc, o, 16));
            float mnew  = fmaxf(m_r[r], mloc);
            float alpha = __expf(m_r[r] - mnew);
            m_r[r] = mnew;
            float rs = 0.f;
#pragma unroll
            for (int c = 0; c < 4; c++) {
                float pv = __expf(s[r][c] - mnew);
                s[r][c] = pv;
                rs += pv;
            }
#pragma unroll
            for (int o = 8; o > 0; o >>= 1)
                rs += __shfl_xor_sync(0xffffffffu, rs, o, 16);
            l_r[r] = l_r[r] * alpha + rs;
#pragma unroll
            for (int c = 0; c < 4; c++) O[r][c] *= alpha;
        }

        // stage P to smem for the PV GEMM
#pragma unroll
        for (int r = 0; r < 4; r++)
            *(float4*)&Ps[((ty << 2) + r) * 68 + (tx << 2)] =
                make_float4(s[r][0], s[r][1], s[r][2], s[r][3]);
        __syncthreads();

        // O += P @ V (outer product over j)
#pragma unroll 4
        for (int j = 0; j < 64; j++) {
            float4 vb = *(const float4*)&Vs[j * 68 + (tx << 2)];
#pragma unroll
            for (int r = 0; r < 4; r++) {
                float a = Ps[((ty << 2) + r) * 68 + j];
                O[r][0] = fmaf(a, vb.x, O[r][0]);
                O[r][1] = fmaf(a, vb.y, O[r][1]);
                O[r][2] = fmaf(a, vb.z, O[r][2]);
                O[r][3] = fmaf(a, vb.w, O[r][3]);
            }
        }
    }

    // normalize and write to [B,S,DIM]
#pragma unroll
    for (int r = 0; r < 4; r++) {
        float inv = 1.0f / l_r[r];
        int sq = qt * 64 + (ty << 2) + r;
        float* dst = Att + (size_t)(b * SEQ + sq) * DIM + h * 64 + (tx << 2);
        *(float4*)dst = make_float4(O[r][0] * inv, O[r][1] * inv,
                                    O[r][2] * inv, O[r][3] * inv);
    }
}

// ---------------------------------------------------------------------------
extern "C" void kernel_launch(void* const* d_in, const int* in_sizes, int n_in,
                              void* d_out, int out_size)
{
    const float* q    = (const float*)d_in[0];
    const float* k    = (const float*)d_in[1];
    const float* v    = (const float*)d_in[2];
    const float* mask = (const float*)d_in[3];
    const float* WQ   = (const float*)d_in[4];
    const float* WK   = (const float*)d_in[5];
    const float* WV   = (const float*)d_in[6];
    const float* WO   = (const float*)d_in[7];
    float* out = (float*)d_out;

    float *Qh, *Kh, *Vh, *Att;
    cudaGetSymbolAddress((void**)&Qh,  g_Qh);
    cudaGetSymbolAddress((void**)&Kh,  g_Kh);
    cudaGetSymbolAddress((void**)&Vh,  g_Vh);
    cudaGetSymbolAddress((void**)&Att, g_Att);

    cudaFuncSetAttribute(flash_kernel,
                         cudaFuncAttributeMaxDynamicSharedMemorySize,
                         FA_SMEM_BYTES);

    dim3 gg(DIM / 128, ROWS / 128);   // (8, 64)
    sgemm_kernel<<<gg, 256>>>(q, WQ, Qh, 1);
    sgemm_kernel<<<gg, 256>>>(k, WK, Kh, 1);
    sgemm_kernel<<<gg, 256>>>(v, WV, Vh, 1);
    flash_kernel<<<dim3(SEQ / 64, HEADS, BATCH), 256, FA_SMEM_BYTES>>>(
        Qh, Kh, Vh, mask, Att);
    sgemm_kernel<<<gg, 256>>>(Att, WO, out, 0);
}

// round 2
// speedup vs baseline: 2.9828x; 2.9828x over previous
#include <cuda_runtime.h>
#include <cstddef>

#define DIM    1024
#define HEADS  16
#define DEPTH  64
#define BATCH  4
#define SEQ    2048
#define ROWS   (BATCH * SEQ)   // 8192

// ---------------- scratch (device globals; no allocation allowed) ----------
__device__ float g_Qh[(size_t)BATCH * HEADS * SEQ * DEPTH];  // [B,H,S,D]
__device__ float g_Kh[(size_t)BATCH * HEADS * SEQ * DEPTH];
__device__ float g_Vh[(size_t)BATCH * HEADS * SEQ * DEPTH];
__device__ float g_Att[(size_t)ROWS * DIM];                  // [B,S,DIM]

// ---------------- tf32 helpers --------------------------------------------
__device__ __forceinline__ unsigned f2tf(float x) {
    unsigned u;
    asm("cvt.rna.tf32.f32 %0, %1;" : "=r"(u) : "f"(x));
    return u;
}
__device__ __forceinline__ float tf(float x) { return __uint_as_float(f2tf(x)); }

// D += A(16x8) * B(8x8), tf32, row.col
__device__ __forceinline__ void mma8(float* d, const unsigned* a, const unsigned* b) {
    asm volatile(
        "mma.sync.aligned.m16n8k8.row.col.f32.tf32.tf32.f32 "
        "{%0,%1,%2,%3},{%4,%5,%6,%7},{%8,%9},{%0,%1,%2,%3};"
        : "+f"(d[0]), "+f"(d[1]), "+f"(d[2]), "+f"(d[3])
        : "r"(a[0]), "r"(a[1]), "r"(a[2]), "r"(a[3]), "r"(b[0]), "r"(b[1]));
}

// ---------------------------------------------------------------------------
// TF32 tensor-core GEMM: C = A[M,1024] @ B[1024,1024].
// Block 128x128, 8 warps (4x2), warp tile 32x64, k-step 16.
// mode 0: C flat [M,1024]. mode 1: C scattered to [B,H,S,D].
// ---------------------------------------------------------------------------
#define AST 20    // As row stride (floats): bank = (20g+tig)%32 all-distinct
#define BST 136   // Bs row stride: bank = (8tig+g)%32 all-distinct

__global__ void __launch_bounds__(256, 2) gemm_tf32(
    const float* __restrict__ A, const float* __restrict__ B,
    float* __restrict__ C, int mode)
{
    __shared__ float As[128 * AST];   // [m][k0..15]
    __shared__ float Bs[16 * BST];    // [k][n0..127]

    const int tid = threadIdx.x, lane = tid & 31, w = tid >> 5;
    const int g = lane >> 2, tg = lane & 3;
    const int wm = (w & 3) << 5;      // 0,32,64,96
    const int wn = (w >> 2) << 6;     // 0,64
    const int m0 = blockIdx.y << 7;
    const int n0 = blockIdx.x << 7;

    const int ar = tid >> 2;          // 0..63 (rows ar, ar+64)
    const int ac = (tid & 3) << 2;    // 0,4,8,12
    const int br = tid >> 5;          // 0..7 (rows br, br+8)
    const int bc = lane << 2;         // 0..124

    float acc[2][8][4];
#pragma unroll
    for (int i = 0; i < 2; i++)
#pragma unroll
        for (int j = 0; j < 8; j++)
#pragma unroll
            for (int c = 0; c < 4; c++) acc[i][j][c] = 0.f;

    const float* Ap0 = A + (size_t)(m0 + ar) * DIM + ac;
    const float* Ap1 = A + (size_t)(m0 + ar + 64) * DIM + ac;

    float4 a0 = *(const float4*)Ap0;
    float4 a1 = *(const float4*)Ap1;
    float4 b0 = *(const float4*)(B + (size_t)br * DIM + n0 + bc);
    float4 b1 = *(const float4*)(B + (size_t)(br + 8) * DIM + n0 + bc);

    for (int kk = 0; kk < DIM; kk += 16) {
        *(float4*)&As[ar * AST + ac] =
            make_float4(tf(a0.x), tf(a0.y), tf(a0.z), tf(a0.w));
        *(float4*)&As[(ar + 64) * AST + ac] =
            make_float4(tf(a1.x), tf(a1.y), tf(a1.z), tf(a1.w));
        *(float4*)&Bs[br * BST + bc] =
            make_float4(tf(b0.x), tf(b0.y), tf(b0.z), tf(b0.w));
        *(float4*)&Bs[(br + 8) * BST + bc] =
            make_float4(tf(b1.x), tf(b1.y), tf(b1.z), tf(b1.w));
        __syncthreads();

        if (kk + 16 < DIM) {
            a0 = *(const float4*)(Ap0 + kk + 16);
            a1 = *(const float4*)(Ap1 + kk + 16);
            b0 = *(const float4*)(B + (size_t)(kk + 16 + br) * DIM + n0 + bc);
            b1 = *(const float4*)(B + (size_t)(kk + 24 + br) * DIM + n0 + bc);
        }

#pragma unroll
        for (int k0 = 0; k0 < 16; k0 += 8) {
            unsigned af[2][4];
#pragma unroll
            for (int mf = 0; mf < 2; mf++) {
                int m = wm + (mf << 4);
                af[mf][0] = __float_as_uint(As[(m + g) * AST + k0 + tg]);
                af[mf][1] = __float_as_uint(As[(m + g + 8) * AST + k0 + tg]);
                af[mf][2] = __float_as_uint(As[(m + g) * AST + k0 + tg + 4]);
                af[mf][3] = __float_as_uint(As[(m + g + 8) * AST + k0 + tg + 4]);
            }
#pragma unroll
            for (int nf = 0; nf < 8; nf++) {
                unsigned bf[2];
                int n = wn + (nf << 3) + g;
                bf[0] = __float_as_uint(Bs[(k0 + tg) * BST + n]);
                bf[1] = __float_as_uint(Bs[(k0 + tg + 4) * BST + n]);
                mma8(acc[0][nf], af[0], bf);
                mma8(acc[1][nf], af[1], bf);
            }
        }
        __syncthreads();
    }

    // epilogue
#pragma unroll
    for (int mf = 0; mf < 2; mf++) {
        int r0 = m0 + wm + (mf << 4) + g;
#pragma unroll
        for (int nf = 0; nf < 8; nf++) {
            int c = n0 + wn + (nf << 3) + (tg << 1);
            if (mode == 0) {
                *(float2*)&C[(size_t)r0 * DIM + c] =
                    make_float2(acc[mf][nf][0], acc[mf][nf][1]);
                *(float2*)&C[(size_t)(r0 + 8) * DIM + c] =
                    make_float2(acc[mf][nf][2], acc[mf][nf][3]);
            } else {
                int h = c >> 6, d = c & 63;
                int bb0 = r0 >> 11, s0 = r0 & 2047;
                int bb1 = (r0 + 8) >> 11, s1 = (r0 + 8) & 2047;
                size_t i0 = (((size_t)(bb0 * HEADS + h) * SEQ + s0) << 6) + d;
                size_t i1 = (((size_t)(bb1 * HEADS + h) * SEQ + s1) << 6) + d;
                *(float2*)&C[i0] = make_float2(acc[mf][nf][0], acc[mf][nf][1]);
                *(float2*)&C[i1] = make_float2(acc[mf][nf][2], acc[mf][nf][3]);
            }
        }
    }
}

// ---------------------------------------------------------------------------
// Flash attention, TF32 tensor cores. Block = (b, h, 128-query tile),
// 256 threads = 8 warps, warp owns 16 q rows. K-tiles of 64.
// smem: Qs[128][68] persistent; R1[128][68] = K[64]|V[64] tiles then P;
// Vt[64][68] = transposed V. Stride 68 -> conflict-free fragment reads.
// ---------------------------------------------------------------------------
#define FST 68
#define FA_SMEM_FLOATS (128 * FST + 128 * FST + 64 * FST + 64)
#define FA_SMEM_BYTES  (FA_SMEM_FLOATS * 4)

__global__ void __launch_bounds__(256, 2) flash_tf32(
    const float* __restrict__ Qh, const float* __restrict__ Kh,
    const float* __restrict__ Vh, const float* __restrict__ Mask,
    float* __restrict__ Att)
{
    extern __shared__ float smf[];
    float* Qs  = smf;                    // 128*68
    float* R1  = smf + 128 * FST;        // 128*68 (K rows 0-63, V rows 64-127; later P)
    float* Vt  = smf + 2 * 128 * FST;    // 64*68  [d][j]
    float* Msh = Vt + 64 * FST;          // 64

    float* Ksm = R1;
    float* Vsm = R1 + 64 * FST;
    float* Ps  = R1;

    const int tid = threadIdx.x, lane = tid & 31, w = tid >> 5;
    const int g = lane >> 2, tg = lane & 3;
    const int q0 = w << 4;               // warp's q-row base (0..112)
    const int b = blockIdx.z, h = blockIdx.y, qt = blockIdx.x;

    const float* Qg = Qh + ((size_t)(b * HEADS + h) * SEQ + qt * 128) * DEPTH;
    const float* Kg = Kh + (size_t)(b * HEADS + h) * SEQ * DEPTH;
    const float* Vg = Vh + (size_t)(b * HEADS + h) * SEQ * DEPTH;
    const float* Mg = Mask + (size_t)b * SEQ;

    // stage Q (pre-scaled by 1/8, tf32) into Qs
#pragma unroll
    for (int it = 0; it < 8; it++) {
        int idx = tid + it * 256;
        int r = idx >> 4, c = (idx & 15) << 2;
        float4 qv = *(const float4*)(Qg + r * DEPTH + c);
        *(float4*)&Qs[r * FST + c] = make_float4(
            tf(0.125f * qv.x), tf(0.125f * qv.y),
            tf(0.125f * qv.z), tf(0.125f * qv.w));
    }

    float o[8][4];
#pragma unroll
    for (int nf = 0; nf < 8; nf++)
#pragma unroll
        for (int c = 0; c < 4; c++) o[nf][c] = 0.f;
    float mrow0 = -1e30f, mrow1 = -1e30f, lrow0 = 0.f, lrow1 = 0.f;

    for (int kt = 0; kt < SEQ / 64; kt++) {
        __syncthreads();                                   // (A)
        const float* Kgt = Kg + kt * 64 * DEPTH;
        const float* Vgt = Vg + kt * 64 * DEPTH;
#pragma unroll
        for (int it = 0; it < 4; it++) {
            int idx = tid + it * 256;
            int r = idx >> 4, c = (idx & 15) << 2;
            float4 kv = *(const float4*)(Kgt + r * DEPTH + c);
            *(float4*)&Ksm[r * FST + c] = make_float4(
                tf(kv.x), tf(kv.y), tf(kv.z), tf(kv.w));
            float4 vv = *(const float4*)(Vgt + r * DEPTH + c);
            *(float4*)&Vsm[r * FST + c] = make_float4(
                tf(vv.x), tf(vv.y), tf(vv.z), tf(vv.w));
        }
        if (tid < 64) Msh[tid] = Mg[kt * 64 + tid] * 1e9f;
        __syncthreads();                                   // (B)

        // transpose V -> Vt[d][j] (conflict-free reads, STS.128 writes)
        {
            int dd = tid & 63;
            int j0 = (tid >> 6) << 4;
#pragma unroll
            for (int jj = 0; jj < 16; jj += 4) {
                float4 t;
                t.x = Vsm[(j0 + jj + 0) * FST + dd];
                t.y = Vsm[(j0 + jj + 1) * FST + dd];
                t.z = Vsm[(j0 + jj + 2) * FST + dd];
                t.w = Vsm[(j0 + jj + 3) * FST + dd];
                *(float4*)&Vt[dd * FST + j0 + jj] = t;
            }
        }

        // S = Q @ K^T (scores, scale already in Q)
        float s[8][4];
#pragma unroll
        for (int nf = 0; nf < 8; nf++)
#pragma unroll
            for (int c = 0; c < 4; c++) s[nf][c] = 0.f;

#pragma unroll
        for (int k0 = 0; k0 < 8; k0++) {
            unsigned qa[4];
            qa[0] = __float_as_uint(Qs[(q0 + g) * FST + (k0 << 3) + tg]);
            qa[1] = __float_as_uint(Qs[(q0 + g + 8) * FST + (k0 << 3) + tg]);
            qa[2] = __float_as_uint(Qs[(q0 + g) * FST + (k0 << 3) + tg + 4]);
            qa[3] = __float_as_uint(Qs[(q0 + g + 8) * FST + (k0 << 3) + tg + 4]);
#pragma unroll
            for (int nf = 0; nf < 8; nf++) {
                unsigned bf[2];
                bf[0] = __float_as_uint(Ksm[((nf << 3) + g) * FST + (k0 << 3) + tg]);
                bf[1] = __float_as_uint(Ksm[((nf << 3) + g) * FST + (k0 << 3) + tg + 4]);
                mma8(s[nf], qa, bf);
            }
        }

        // mask + online softmax (rows g, g+8 of warp tile)
        float mx0 = -1e30f, mx1 = -1e30f;
#pragma unroll
        for (int nf = 0; nf < 8; nf++) {
            float k0v = Msh[(nf << 3) + (tg << 1)];
            float k1v = Msh[(nf << 3) + (tg << 1) + 1];
            s[nf][0] -= k0v; s[nf][1] -= k1v;
            s[nf][2] -= k0v; s[nf][3] -= k1v;
            mx0 = fmaxf(mx0, fmaxf(s[nf][0], s[nf][1]));
            mx1 = fmaxf(mx1, fmaxf(s[nf][2], s[nf][3]));
        }
        mx0 = fmaxf(mx0, __shfl_xor_sync(0xffffffffu, mx0, 1));
        mx0 = fmaxf(mx0, __shfl_xor_sync(0xffffffffu, mx0, 2));
        mx1 = fmaxf(mx1, __shfl_xor_sync(0xffffffffu, mx1, 1));
        mx1 = fmaxf(mx1, __shfl_xor_sync(0xffffffffu, mx1, 2));

        float mn0 = fmaxf(mrow0, mx0), mn1 = fmaxf(mrow1, mx1);
        float al0 = __expf(mrow0 - mn0), al1 = __expf(mrow1 - mn1);
        mrow0 = mn0; mrow1 = mn1;

        float sm0 = 0.f, sm1 = 0.f;
#pragma unroll
        for (int nf = 0; nf < 8; nf++) {
            s[nf][0] = __expf(s[nf][0] - mn0);
            s[nf][1] = __expf(s[nf][1] - mn0);
            s[nf][2] = __expf(s[nf][2] - mn1);
            s[nf][3] = __expf(s[nf][3] - mn1);
            sm0 += s[nf][0] + s[nf][1];
            sm1 += s[nf][2] + s[nf][3];
        }
        sm0 += __shfl_xor_sync(0xffffffffu, sm0, 1);
        sm0 += __shfl_xor_sync(0xffffffffu, sm0, 2);
        sm1 += __shfl_xor_sync(0xffffffffu, sm1, 1);
        sm1 += __shfl_xor_sync(0xffffffffu, sm1, 2);
        lrow0 = lrow0 * al0 + sm0;
        lrow1 = lrow1 * al1 + sm1;
#pragma unroll
        for (int nf = 0; nf < 8; nf++) {
            o[nf][0] *= al0; o[nf][1] *= al0;
            o[nf][2] *= al1; o[nf][3] *= al1;
        }

        __syncthreads();                                   // (C) Vt ready, K reads done

        // P -> smem (C-layout write, A-layout read; warp-private rows)
#pragma unroll
        for (int nf = 0; nf < 8; nf++) {
            *(float2*)&Ps[(q0 + g) * FST + (nf << 3) + (tg << 1)] =
                make_float2(s[nf][0], s[nf][1]);
            *(float2*)&Ps[(q0 + g + 8) * FST + (nf << 3) + (tg << 1)] =
                make_float2(s[nf][2], s[nf][3]);
        }
        __syncwarp();

        // O += P @ V
#pragma unroll
        for (int j0 = 0; j0 < 8; j0++) {
            unsigned pa[4];
            pa[0] = __float_as_uint(Ps[(q0 + g) * FST + (j0 << 3) + tg]);
            pa[1] = __float_as_uint(Ps[(q0 + g + 8) * FST + (j0 << 3) + tg]);
            pa[2] = __float_as_uint(Ps[(q0 + g) * FST + (j0 << 3) + tg + 4]);
            pa[3] = __float_as_uint(Ps[(q0 + g + 8) * FST + (j0 << 3) + tg + 4]);
#pragma unroll
            for (int nf = 0; nf < 8; nf++) {
                unsigned bf[2];
                bf[0] = __float_as_uint(Vt[((nf << 3) + g) * FST + (j0 << 3) + tg]);
                bf[1] = __float_as_uint(Vt[((nf << 3) + g) * FST + (j0 << 3) + tg + 4]);
                mma8(o[nf], pa, bf);
            }
        }
    }

    // normalize + write [B,S,DIM]
    float inv0 = 1.0f / lrow0, inv1 = 1.0f / lrow1;
    int r0 = qt * 128 + q0 + g;
    int r1 = r0 + 8;
#pragma unroll
    for (int nf = 0; nf < 8; nf++) {
        int c = h * 64 + (nf << 3) + (tg << 1);
        *(float2*)&Att[(size_t)(b * SEQ + r0) * DIM + c] =
            make_float2(o[nf][0] * inv0, o[nf][1] * inv0);
        *(float2*)&Att[(size_t)(b * SEQ + r1) * DIM + c] =
            make_float2(o[nf][2] * inv1, o[nf][3] * inv1);
    }
}

// ---------------------------------------------------------------------------
extern "C" void kernel_launch(void* const* d_in, const int* in_sizes, int n_in,
                              void* d_out, int out_size)
{
    const float* q    = (const float*)d_in[0];
    const float* k    = (const float*)d_in[1];
    const float* v    = (const float*)d_in[2];
    const float* mask = (const float*)d_in[3];
    const float* WQ   = (const float*)d_in[4];
    const float* WK   = (const float*)d_in[5];
    const float* WV   = (const float*)d_in[6];
    const float* WO   = (const float*)d_in[7];
    float* out = (float*)d_out;

    float *Qh, *Kh, *Vh, *Att;
    cudaGetSymbolAddress((void**)&Qh,  g_Qh);
    cudaGetSymbolAddress((void**)&Kh,  g_Kh);
    cudaGetSymbolAddress((void**)&Vh,  g_Vh);
    cudaGetSymbolAddress((void**)&Att, g_Att);

    cudaFuncSetAttribute(flash_tf32,
                         cudaFuncAttributeMaxDynamicSharedMemorySize,
                         FA_SMEM_BYTES);

    dim3 gg(DIM / 128, ROWS / 128);   // (8, 64)
    gemm_tf32<<<gg, 256>>>(q, WQ, Qh, 1);
    gemm_tf32<<<gg, 256>>>(k, WK, Kh, 1);
    gemm_tf32<<<gg, 256>>>(v, WV, Vh, 1);
    flash_tf32<<<dim3(SEQ / 128, HEADS, BATCH), 256, FA_SMEM_BYTES>>>(
        Qh, Kh, Vh, mask, Att);
    gemm_tf32<<<gg, 256>>>(Att, WO, out, 0);
}

// round 3
// speedup vs baseline: 3.7155x; 1.2456x over previous
#include <cuda_runtime.h>
#include <cstddef>

#define DIM    1024
#define HEADS  16
#define DEPTH  64
#define BATCH  4
#define SEQ    2048
#define ROWS   (BATCH * SEQ)   // 8192

// ---------------- scratch (device globals; no allocation allowed) ----------
__device__ float g_Qh[(size_t)BATCH * HEADS * SEQ * DEPTH];  // [B,H,S,D]
__device__ float g_Kh[(size_t)BATCH * HEADS * SEQ * DEPTH];
__device__ float g_Vh[(size_t)BATCH * HEADS * SEQ * DEPTH];
__device__ float g_Att[(size_t)ROWS * DIM];                  // [B,S,DIM]

// ---------------- tf32 helpers --------------------------------------------
__device__ __forceinline__ unsigned f2tf(float x) {
    unsigned u;
    asm("cvt.rna.tf32.f32 %0, %1;" : "=r"(u) : "f"(x));
    return u;
}
__device__ __forceinline__ float tf(float x) { return __uint_as_float(f2tf(x)); }
__device__ __forceinline__ float4 tf4(float4 v) {
    return make_float4(tf(v.x), tf(v.y), tf(v.z), tf(v.w));
}

// D += A(16x8) * B(8x8), tf32, row.col
__device__ __forceinline__ void mma8(float* d, const unsigned* a, const unsigned* b) {
    asm volatile(
        "mma.sync.aligned.m16n8k8.row.col.f32.tf32.tf32.f32 "
        "{%0,%1,%2,%3},{%4,%5,%6,%7},{%8,%9},{%0,%1,%2,%3};"
        : "+f"(d[0]), "+f"(d[1]), "+f"(d[2]), "+f"(d[3])
        : "r"(a[0]), "r"(a[1]), "r"(a[2]), "r"(a[3]), "r"(b[0]), "r"(b[1]));
}

// ---------------------------------------------------------------------------
// TF32 GEMM: C = A[M,1024] @ B[1024,1024].
// Block 128x128, 128 threads = 4 warps (2x2), warp tile 64x64, k-step 16.
// mode 0: C flat [M,1024]. mode 1: C scattered to [B,H,S,D].
// ---------------------------------------------------------------------------
#define AST 20    // banks (20g+tg)%32 all distinct for A-frag loads
#define BST 140   // banks (12tg+g)%32 all distinct for B-frag loads

__global__ void __launch_bounds__(128, 2) gemm_tf32(
    const float* __restrict__ A, const float* __restrict__ B,
    float* __restrict__ C, int mode)
{
    __shared__ float As[128 * AST];   // [m][k0..15]
    __shared__ float Bs[16 * BST];    // [k][n0..127]

    const int tid = threadIdx.x, lane = tid & 31, w = tid >> 5;
    const int g = lane >> 2, tg = lane & 3;
    const int wm = (w & 1) << 6;      // 0,64
    const int wn = (w >> 1) << 6;     // 0,64
    const int m0 = blockIdx.y << 7;
    const int n0 = blockIdx.x << 7;

    // staging: A rows ar+32j (j=0..3), one float4 of k each
    const int ar = tid >> 2;          // 0..31
    const int ac = (tid & 3) << 2;    // 0,4,8,12
    // staging: B rows br+4j, contiguous 128-float rows
    const int br = tid >> 5;          // 0..3
    const int bc = lane << 2;         // 0..124

    float acc[4][8][4];
#pragma unroll
    for (int i = 0; i < 4; i++)
#pragma unroll
        for (int j = 0; j < 8; j++)
#pragma unroll
            for (int c = 0; c < 4; c++) acc[i][j][c] = 0.f;

    float4 pa[4], pb[4];
#pragma unroll
    for (int j = 0; j < 4; j++) {
        pa[j] = *(const float4*)(A + (size_t)(m0 + ar + 32 * j) * DIM + ac);
        pb[j] = *(const float4*)(B + (size_t)(br + 4 * j) * DIM + n0 + bc);
    }

    for (int kk = 0; kk < DIM; kk += 16) {
#pragma unroll
        for (int j = 0; j < 4; j++) {
            *(float4*)&As[(ar + 32 * j) * AST + ac] = tf4(pa[j]);
            *(float4*)&Bs[(br + 4 * j) * BST + bc]  = tf4(pb[j]);
        }
        __syncthreads();

        if (kk + 16 < DIM) {
#pragma unroll
            for (int j = 0; j < 4; j++) {
                pa[j] = *(const float4*)(A + (size_t)(m0 + ar + 32 * j) * DIM + kk + 16 + ac);
                pb[j] = *(const float4*)(B + (size_t)(kk + 16 + br + 4 * j) * DIM + n0 + bc);
            }
        }

#pragma unroll
        for (int k0 = 0; k0 < 16; k0 += 8) {
            unsigned af[4][4];
#pragma unroll
            for (int mf = 0; mf < 4; mf++) {
                int m = wm + (mf << 4);
                af[mf][0] = __float_as_uint(As[(m + g) * AST + k0 + tg]);
                af[mf][1] = __float_as_uint(As[(m + g + 8) * AST + k0 + tg]);
                af[mf][2] = __float_as_uint(As[(m + g) * AST + k0 + tg + 4]);
                af[mf][3] = __float_as_uint(As[(m + g + 8) * AST + k0 + tg + 4]);
            }
#pragma unroll
            for (int nf = 0; nf < 8; nf++) {
                unsigned bf[2];
                int n = wn + (nf << 3) + g;
                bf[0] = __float_as_uint(Bs[(k0 + tg) * BST + n]);
                bf[1] = __float_as_uint(Bs[(k0 + tg + 4) * BST + n]);
#pragma unroll
                for (int mf = 0; mf < 4; mf++)
                    mma8(acc[mf][nf], af[mf], bf);
            }
        }
        __syncthreads();
    }

    // epilogue
#pragma unroll
    for (int mf = 0; mf < 4; mf++) {
        int r0 = m0 + wm + (mf << 4) + g;
#pragma unroll
        for (int nf = 0; nf < 8; nf++) {
            int c = n0 + wn + (nf << 3) + (tg << 1);
            if (mode == 0) {
                *(float2*)&C[(size_t)r0 * DIM + c] =
                    make_float2(acc[mf][nf][0], acc[mf][nf][1]);
                *(float2*)&C[(size_t)(r0 + 8) * DIM + c] =
                    make_float2(acc[mf][nf][2], acc[mf][nf][3]);
            } else {
                int h = c >> 6, d = c & 63;
                int bb0 = r0 >> 11, s0 = r0 & 2047;
                int bb1 = (r0 + 8) >> 11, s1 = (r0 + 8) & 2047;
                size_t i0 = (((size_t)(bb0 * HEADS + h) * SEQ + s0) << 6) + d;
                size_t i1 = (((size_t)(bb1 * HEADS + h) * SEQ + s1) << 6) + d;
                *(float2*)&C[i0] = make_float2(acc[mf][nf][0], acc[mf][nf][1]);
                *(float2*)&C[i1] = make_float2(acc[mf][nf][2], acc[mf][nf][3]);
            }
        }
    }
}

// ---------------------------------------------------------------------------
// Flash attention, TF32 tensor cores. Block = (b, h, 128-query tile),
// 128 threads = 4 warps, warp owns 32 q rows (two 16-row A-frags share
// every B-frag). K-tiles of 64.
// ---------------------------------------------------------------------------
#define FST 68
#define FA_SMEM_FLOATS (128 * FST + 128 * FST + 64 * FST + 64)
#define FA_SMEM_BYTES  (FA_SMEM_FLOATS * 4)

__global__ void __launch_bounds__(128, 2) flash_tf32(
    const float* __restrict__ Qh, const float* __restrict__ Kh,
    const float* __restrict__ Vh, const float* __restrict__ Mask,
    float* __restrict__ Att)
{
    extern __shared__ float smf[];
    float* Qs  = smf;                    // 128*68
    float* R1  = smf + 128 * FST;        // K rows 0-63 | V rows 64-127; later P
    float* Vt  = smf + 2 * 128 * FST;    // 64*68  [d][j]
    float* Msh = Vt + 64 * FST;          // 64

    float* Ksm = R1;
    float* Vsm = R1 + 64 * FST;
    float* Ps  = R1;

    const int tid = threadIdx.x, lane = tid & 31, w = tid >> 5;
    const int g = lane >> 2, tg = lane & 3;
    const int q0 = w << 5;               // warp q-row base: 0,32,64,96
    const int b = blockIdx.z, h = blockIdx.y, qt = blockIdx.x;

    const float* Qg = Qh + ((size_t)(b * HEADS + h) * SEQ + qt * 128) * DEPTH;
    const float* Kg = Kh + (size_t)(b * HEADS + h) * SEQ * DEPTH;
    const float* Vg = Vh + (size_t)(b * HEADS + h) * SEQ * DEPTH;
    const float* Mg = Mask + (size_t)b * SEQ;

    // stage Q (pre-scaled by 1/8, tf32)
#pragma unroll
    for (int it = 0; it < 16; it++) {
        int idx = tid + it * 128;
        int r = idx >> 4, c = (idx & 15) << 2;
        float4 qv = *(const float4*)(Qg + r * DEPTH + c);
        *(float4*)&Qs[r * FST + c] = make_float4(
            tf(0.125f * qv.x), tf(0.125f * qv.y),
            tf(0.125f * qv.z), tf(0.125f * qv.w));
    }

    float o[2][8][4];
#pragma unroll
    for (int mf = 0; mf < 2; mf++)
#pragma unroll
        for (int nf = 0; nf < 8; nf++)
#pragma unroll
            for (int c = 0; c < 4; c++) o[mf][nf][c] = 0.f;
    float mrow[4] = {-1e30f, -1e30f, -1e30f, -1e30f};
    float lrow[4] = {0.f, 0.f, 0.f, 0.f};

    for (int kt = 0; kt < SEQ / 64; kt++) {
        __syncthreads();                                   // (A) prev P/Vt reads done
        const float* Kgt = Kg + kt * 64 * DEPTH;
        const float* Vgt = Vg + kt * 64 * DEPTH;
#pragma unroll
        for (int it = 0; it < 8; it++) {
            int idx = tid + it * 128;
            int r = idx >> 4, c = (idx & 15) << 2;
            *(float4*)&Ksm[r * FST + c] = tf4(*(const float4*)(Kgt + r * DEPTH + c));
            *(float4*)&Vsm[r * FST + c] = tf4(*(const float4*)(Vgt + r * DEPTH + c));
        }
        if (tid < 64) Msh[tid] = Mg[kt * 64 + tid] * 1e9f;
        __syncthreads();                                   // (B) tiles ready

        // transpose V -> Vt[d][j]
        {
            int dd = tid & 63;
            int j0 = (tid >> 6) << 5;
#pragma unroll
            for (int jj = 0; jj < 32; jj += 4) {
                float4 t;
                t.x = Vsm[(j0 + jj + 0) * FST + dd];
                t.y = Vsm[(j0 + jj + 1) * FST + dd];
                t.z = Vsm[(j0 + jj + 2) * FST + dd];
                t.w = Vsm[(j0 + jj + 3) * FST + dd];
                *(float4*)&Vt[dd * FST + j0 + jj] = t;
            }
        }

        // S = Q @ K^T (scale folded into Q)
        float s[2][8][4];
#pragma unroll
        for (int mf = 0; mf < 2; mf++)
#pragma unroll
            for (int nf = 0; nf < 8; nf++)
#pragma unroll
                for (int c = 0; c < 4; c++) s[mf][nf][c] = 0.f;

#pragma unroll
        for (int k0 = 0; k0 < 8; k0++) {
            unsigned qa[2][4];
#pragma unroll
            for (int mf = 0; mf < 2; mf++) {
                int m = q0 + (mf << 4);
                qa[mf][0] = __float_as_uint(Qs[(m + g) * FST + (k0 << 3) + tg]);
                qa[mf][1] = __float_as_uint(Qs[(m + g + 8) * FST + (k0 << 3) + tg]);
                qa[mf][2] = __float_as_uint(Qs[(m + g) * FST + (k0 << 3) + tg + 4]);
                qa[mf][3] = __float_as_uint(Qs[(m + g + 8) * FST + (k0 << 3) + tg + 4]);
            }
#pragma unroll
            for (int nf = 0; nf < 8; nf++) {
                unsigned bf[2];
                bf[0] = __float_as_uint(Ksm[((nf << 3) + g) * FST + (k0 << 3) + tg]);
                bf[1] = __float_as_uint(Ksm[((nf << 3) + g) * FST + (k0 << 3) + tg + 4]);
                mma8(s[0][nf], qa[0], bf);
                mma8(s[1][nf], qa[1], bf);
            }
        }

        // mask + online softmax; lane rows: [mf*16+g (c01), mf*16+g+8 (c23)]
        float mx[4] = {-1e30f, -1e30f, -1e30f, -1e30f};
#pragma unroll
        for (int mf = 0; mf < 2; mf++)
#pragma unroll
            for (int nf = 0; nf < 8; nf++) {
                float k0v = Msh[(nf << 3) + (tg << 1)];
                float k1v = Msh[(nf << 3) + (tg << 1) + 1];
                s[mf][nf][0] -= k0v; s[mf][nf][1] -= k1v;
                s[mf][nf][2] -= k0v; s[mf][nf][3] -= k1v;
                mx[mf * 2 + 0] = fmaxf(mx[mf * 2 + 0], fmaxf(s[mf][nf][0], s[mf][nf][1]));
                mx[mf * 2 + 1] = fmaxf(mx[mf * 2 + 1], fmaxf(s[mf][nf][2], s[mf][nf][3]));
            }
#pragma unroll
        for (int r = 0; r < 4; r++) {
            mx[r] = fmaxf(mx[r], __shfl_xor_sync(0xffffffffu, mx[r], 1));
            mx[r] = fmaxf(mx[r], __shfl_xor_sync(0xffffffffu, mx[r], 2));
        }
        float al[4];
#pragma unroll
        for (int r = 0; r < 4; r++) {
            float mn = fmaxf(mrow[r], mx[r]);
            al[r] = __expf(mrow[r] - mn);
            mrow[r] = mn;
        }
        float sm[4] = {0.f, 0.f, 0.f, 0.f};
#pragma unroll
        for (int mf = 0; mf < 2; mf++)
#pragma unroll
            for (int nf = 0; nf < 8; nf++) {
                s[mf][nf][0] = __expf(s[mf][nf][0] - mrow[mf * 2 + 0]);
                s[mf][nf][1] = __expf(s[mf][nf][1] - mrow[mf * 2 + 0]);
                s[mf][nf][2] = __expf(s[mf][nf][2] - mrow[mf * 2 + 1]);
                s[mf][nf][3] = __expf(s[mf][nf][3] - mrow[mf * 2 + 1]);
                sm[mf * 2 + 0] += s[mf][nf][0] + s[mf][nf][1];
                sm[mf * 2 + 1] += s[mf][nf][2] + s[mf][nf][3];
            }
#pragma unroll
        for (int r = 0; r < 4; r++) {
            sm[r] += __shfl_xor_sync(0xffffffffu, sm[r], 1);
            sm[r] += __shfl_xor_sync(0xffffffffu, sm[r], 2);
            lrow[r] = lrow[r] * al[r] + sm[r];
        }
#pragma unroll
        for (int mf = 0; mf < 2; mf++)
#pragma unroll
            for (int nf = 0; nf < 8; nf++) {
                o[mf][nf][0] *= al[mf * 2 + 0]; o[mf][nf][1] *= al[mf * 2 + 0];
                o[mf][nf][2] *= al[mf * 2 + 1]; o[mf][nf][3] *= al[mf * 2 + 1];
            }

        __syncthreads();           // (C) Vt written; K-tile reads done

        // P -> smem (rows warp-private)
#pragma unroll
        for (int mf = 0; mf < 2; mf++) {
            int m = q0 + (mf << 4);
#pragma unroll
            for (int nf = 0; nf < 8; nf++) {
                *(float2*)&Ps[(m + g) * FST + (nf << 3) + (tg << 1)] =
                    make_float2(s[mf][nf][0], s[mf][nf][1]);
                *(float2*)&Ps[(m + g + 8) * FST + (nf << 3) + (tg << 1)] =
                    make_float2(s[mf][nf][2], s[mf][nf][3]);
            }
        }
        __syncwarp();

        // O += P @ V
#pragma unroll
        for (int j0 = 0; j0 < 8; j0++) {
            unsigned pa[2][4];
#pragma unroll
            for (int mf = 0; mf < 2; mf++) {
                int m = q0 + (mf << 4);
                pa[mf][0] = __float_as_uint(Ps[(m + g) * FST + (j0 << 3) + tg]);
                pa[mf][1] = __float_as_uint(Ps[(m + g + 8) * FST + (j0 << 3) + tg]);
                pa[mf][2] = __float_as_uint(Ps[(m + g) * FST + (j0 << 3) + tg + 4]);
                pa[mf][3] = __float_as_uint(Ps[(m + g + 8) * FST + (j0 << 3) + tg + 4]);
            }
#pragma unroll
            for (int nf = 0; nf < 8; nf++) {
                unsigned bf[2];
                bf[0] = __float_as_uint(Vt[((nf << 3) + g) * FST + (j0 << 3) + tg]);
                bf[1] = __float_as_uint(Vt[((nf << 3) + g) * FST + (j0 << 3) + tg + 4]);
                mma8(o[0][nf], pa[0], bf);
                mma8(o[1][nf], pa[1], bf);
            }
        }
    }

    // normalize + write [B,S,DIM]
#pragma unroll
    for (int mf = 0; mf < 2; mf++) {
        float inv0 = 1.0f / lrow[mf * 2 + 0];
        float inv1 = 1.0f / lrow[mf * 2 + 1];
        int r0 = qt * 128 + q0 + (mf << 4) + g;
        int r1 = r0 + 8;
#pragma unroll
        for (int nf = 0; nf < 8; nf++) {
            int c = h * 64 + (nf << 3) + (tg << 1);
            *(float2*)&Att[(size_t)(b * SEQ + r0) * DIM + c] =
                make_float2(o[mf][nf][0] * inv0, o[mf][nf][1] * inv0);
            *(float2*)&Att[(size_t)(b * SEQ + r1) * DIM + c] =
                make_float2(o[mf][nf][2] * inv1, o[mf][nf][3] * inv1);
        }
    }
}

// ---------------------------------------------------------------------------
extern "C" void kernel_launch(void* const* d_in, const int* in_sizes, int n_in,
                              void* d_out, int out_size)
{
    const float* q    = (const float*)d_in[0];
    const float* k    = (const float*)d_in[1];
    const float* v    = (const float*)d_in[2];
    const float* mask = (const float*)d_in[3];
    const float* WQ   = (const float*)d_in[4];
    const float* WK   = (const float*)d_in[5];
    const float* WV   = (const float*)d_in[6];
    const float* WO   = (const float*)d_in[7];
    float* out = (float*)d_out;

    float *Qh, *Kh, *Vh, *Att;
    cudaGetSymbolAddress((void**)&Qh,  g_Qh);
    cudaGetSymbolAddress((void**)&Kh,  g_Kh);
    cudaGetSymbolAddress((void**)&Vh,  g_Vh);
    cudaGetSymbolAddress((void**)&Att, g_Att);

    cudaFuncSetAttribute(flash_tf32,
                         cudaFuncAttributeMaxDynamicSharedMemorySize,
                         FA_SMEM_BYTES);

    dim3 gg(DIM / 128, ROWS / 128);   // (8, 64)
    gemm_tf32<<<gg, 128>>>(q, WQ, Qh, 1);
    gemm_tf32<<<gg, 128>>>(k, WK, Kh, 1);
    gemm_tf32<<<gg, 128>>>(v, WV, Vh, 1);
    flash_tf32<<<dim3(SEQ / 128, HEADS, BATCH), 128, FA_SMEM_BYTES>>>(
        Qh, Kh, Vh, mask, Att);
    gemm_tf32<<<gg, 128>>>(Att, WO, out, 0);
}